// round 15
// baseline (speedup 1.0000x reference)
#include <cuda_runtime.h>
#include <cstdint>

// Problem constants
#define Bn    8
#define Tn    32
#define DIN   768
#define DSAE  8192
#define TOPK  64
#define MROWS 256
#define XHAT_ELEMS (MROWS * DIN)
#define Z_ELEMS    ((size_t)MROWS * DSAE)
#define WCAP  48

// GEMM tiling: 128 threads, 64m x 64n, warp tile 32x32
#define MTW   64
#define NTW   64
#define KB    32
#define STAGES 4               // A fp32 stages
#define KB_PER_CHUNK 96
#define NCHUNK 20
#define A_STR 36
#define A_BYTES (MTW * A_STR * 4)       // 9216 per stage (A only)
// B bf16 tiles: [n=64][kpair=16 words], row stride 20 words (80 B), hi+lo
#define BROW_W 20
#define BTILE_BYTES (64 * BROW_W * 4)   // 5120 per (hi or lo)
#define BBUF_BYTES (2 * BTILE_BYTES)    // 10240 per buffer (hi+lo)
#define B_BASE (STAGES * A_BYTES)       // 36864
#define SMEM_TOTAL (B_BASE + 2 * BBUF_BYTES)   // 57344

// ---------------- scratch (no allocations allowed) ----------------
__device__ float g_pre[(size_t)MROWS * DSAE];                 // t-major
__device__ float g_part[(size_t)NCHUNK * 128 * 4096];         // split-K partials
__device__ int   g_idx[MROWS * TOPK];
__device__ float g_val[MROWS * TOPK];
__device__ int   g_cnt[MROWS];
__device__ unsigned long long g_loss_acc;
__device__ int   g_done_ctr;

// ================= helpers (plain sm_80+ PTX only) =================
__device__ __forceinline__ uint32_t smem_u32(const void* p) {
    uint32_t a;
    asm("{ .reg .u64 t; cvta.to.shared.u64 t, %1; cvt.u32.u64 %0, t; }" : "=r"(a) : "l"(p));
    return a;
}
__device__ __forceinline__ void cp16(uint32_t dst, const void* src, int srcsize) {
    asm volatile("cp.async.cg.shared.global [%0], [%1], 16, %2;"
                 :: "r"(dst), "l"(src), "r"(srcsize) : "memory");
}
#define CP_COMMIT() asm volatile("cp.async.commit_group;" ::: "memory")
#define CP_WAIT2()  asm volatile("cp.async.wait_group 2;" ::: "memory")

// bf16 pair split: h = packed trunc-bf16(v0 lo-half, v1 hi-half); l = remainders
__device__ __forceinline__ void bsplit2(float v0, float v1, uint32_t& h, uint32_t& l) {
    const uint32_t u0 = __float_as_uint(v0), u1 = __float_as_uint(v1);
    h = __byte_perm(u0, u1, 0x7632);
    const float l0 = v0 - __uint_as_float(u0 & 0xFFFF0000u);
    const float l1 = v1 - __uint_as_float(u1 & 0xFFFF0000u);
    l = __byte_perm(__float_as_uint(l0), __float_as_uint(l1), 0x7632);
}

__device__ __forceinline__ void mma16(float* c, const uint32_t* a, const uint32_t* b) {
    asm volatile(
        "mma.sync.aligned.m16n8k16.row.col.f32.bf16.bf16.f32 "
        "{%0,%1,%2,%3}, {%4,%5,%6,%7}, {%8,%9}, {%0,%1,%2,%3};"
        : "+f"(c[0]), "+f"(c[1]), "+f"(c[2]), "+f"(c[3])
        : "r"(a[0]), "r"(a[1]), "r"(a[2]), "r"(a[3]), "r"(b[0]), "r"(b[1]));
}

// =====================================================================
// A stage copy (fp32 cp.async): 64m x 32k causal im2col, zero-fill.
// =====================================================================
__device__ __forceinline__ void copy_stage_A(
    uint32_t sbase, int kb, int m0, const float* __restrict__ x, int tid)
{
#pragma unroll
    for (int q = 0; q < 4; ++q) {
        const int ch  = tid + q * 128;
        const int row = ch >> 3, c4 = ch & 7;
        const int kg  = kb * KB + c4 * 4;
        const int off = kg / DIN;
        const int d   = kg - off * DIN;
        const int mrow = m0 + row;
        const int t = mrow >> 3, b = mrow & 7;
        const bool ok = (off <= t);
        const int  tt = ok ? (t - off) : 0;
        const float* src = x + ((b * Tn + tt) * DIN + d);
        cp16(sbase + row * (A_STR * 4) + c4 * 16, src, ok ? 16 : 0);
    }
}

// =====================================================================
// Dummy kernel (ncu alignment) + global accumulator reset.
// =====================================================================
__global__ void dummy_kernel() {
    if (threadIdx.x == 0 && blockIdx.x == 0) { g_loss_acc = 0ULL; g_done_ctr = 0; }
}

// =====================================================================
// Kernel 1: encoder GEMM, bf16x3, SPLIT-K.
// B path: LDG -> reg split -> packed bf16 [n][kpair] smem (split once,
// no fp32 staging round trip). A path: R12 fp32 stage + consumer split.
// =====================================================================
__global__ __launch_bounds__(128, 3) void enc_mma_kernel(
    const float* __restrict__ x,
    const float* __restrict__ W)
{
    extern __shared__ char smc[];
    const uint32_t smb = smem_u32(smc);
    const int tid = threadIdx.x, lane = tid & 31, wid = tid >> 5;
    const int c  = blockIdx.x;
    const int ny = blockIdx.y;
    const int s0 = ny * NTW;
    const int g  = (c < 2) ? 0 : (c < 6) ? 1 : (c < 12) ? 2 : 3;
    const int kb0 = (c - g * (g + 1)) * KB_PER_CHUNK;
    const int m0  = g * MTW;
    const int wm  = (wid & 1) * 32, wn = (wid >> 1) * 32;

    // B producer mapping: thread owns k rows (2*kpair, 2*kpair+1), n nq8..nq8+7
    const int kpair = tid >> 3;          // 0..15
    const int nq8   = (tid & 7) * 8;     // n base
    const int jrot  = tid & 7;           // STS stagger

    float acc[2][4][4];
#pragma unroll
    for (int a = 0; a < 2; ++a)
#pragma unroll
        for (int b = 0; b < 4; ++b)
#pragma unroll
            for (int cc = 0; cc < 4; ++cc) acc[a][b][cc] = 0.f;

    float4 bset[2][4];   // [set][e0,e1,o0,o1]: k-even n(0..3,4..7), k-odd n(0..3,4..7)

    // ---- B LDG: kblock kb -> set ----
    auto ldgB = [&](int kb, int s) {
        const float* w0 = W + (size_t)(kb * KB + 2 * kpair) * DSAE + s0 + nq8;
        bset[s][0] = *(const float4*)(w0);
        bset[s][1] = *(const float4*)(w0 + 4);
        bset[s][2] = *(const float4*)(w0 + DSAE);
        bset[s][3] = *(const float4*)(w0 + DSAE + 4);
    };
    // ---- B STS: set -> bf16 buffer ----
    auto stsB = [&](int s, int buf) {
        float ev[8] = { bset[s][0].x, bset[s][0].y, bset[s][0].z, bset[s][0].w,
                        bset[s][1].x, bset[s][1].y, bset[s][1].z, bset[s][1].w };
        float od[8] = { bset[s][2].x, bset[s][2].y, bset[s][2].z, bset[s][2].w,
                        bset[s][3].x, bset[s][3].y, bset[s][3].z, bset[s][3].w };
        char* base = smc + B_BASE + buf * BBUF_BYTES;
#pragma unroll
        for (int jj = 0; jj < 8; ++jj) {
            const int j = (jj + jrot) & 7;        // bank stagger
            uint32_t h, l;
            bsplit2(ev[j], od[j], h, l);          // k-even low, k-odd high
            const int n = nq8 + j;
            *(uint32_t*)(base + n * (BROW_W * 4) + kpair * 4) = h;
            *(uint32_t*)(base + BTILE_BYTES + n * (BROW_W * 4) + kpair * 4) = l;
        }
    };

    // prologue: A stages 0..2; B kb0 -> buf0, B kb1 -> set1
#pragma unroll
    for (int p = 0; p < STAGES - 1; ++p) {
        copy_stage_A(smb + p * A_BYTES, kb0 + p, m0, x, tid);
        CP_COMMIT();
    }
    ldgB(kb0 + 0, 0);
    stsB(0, 0);
    ldgB(kb0 + 1, 1);

    const int rA = lane >> 2;
    const int cA = lane & 3;

    for (int i = 0; i < KB_PER_CHUNK; ++i) {
        CP_WAIT2();
        __syncthreads();   // A stage i ready; prior iter's reads done

        // producer: STS kb(i+1) -> buf (i+1)&1; refill set with kb(i+2)
        if (i + 1 < KB_PER_CHUNK) {
            stsB((i + 1) & 1, (i + 1) & 1);
            if (i + 2 < KB_PER_CHUNK) ldgB(kb0 + i + 2, i & 1);
        }
        // A cp.async prefetch
        const int nx = i + STAGES - 1;
        if (nx < KB_PER_CHUNK) {
            copy_stage_A(smb + (nx & 3) * A_BYTES, kb0 + nx, m0, x, tid);
        }
        CP_COMMIT();

        const float* As = (const float*)(smc + (i & 3) * A_BYTES);
        const char*  bB = smc + B_BASE + (i & 1) * BBUF_BYTES;
        const float* Ar0 = As + (wm + rA) * A_STR + cA * 2;
        const float* Ar1 = As + (wm + 16 + rA) * A_STR + cA * 2;

#pragma unroll
        for (int ksl = 0; ksl < 2; ++ksl) {
            const int kb16 = ksl * 16;
            uint32_t ah[2][4], al[2][4];
#pragma unroll
            for (int mt = 0; mt < 2; ++mt) {
                const float* ap = (mt == 0) ? Ar0 : Ar1;
                float2 p0 = *(const float2*)(ap + kb16);
                float2 p1 = *(const float2*)(ap + 8 * A_STR + kb16);
                float2 p2 = *(const float2*)(ap + kb16 + 8);
                float2 p3 = *(const float2*)(ap + 8 * A_STR + kb16 + 8);
                bsplit2(p0.x, p0.y, ah[mt][0], al[mt][0]);
                bsplit2(p1.x, p1.y, ah[mt][1], al[mt][1]);
                bsplit2(p2.x, p2.y, ah[mt][2], al[mt][2]);
                bsplit2(p3.x, p3.y, ah[mt][3], al[mt][3]);
            }
            uint32_t bh[4][2], bl[4][2];
#pragma unroll
            for (int nt = 0; nt < 4; ++nt) {
                const int n = wn + nt * 8 + rA;
                const char* rowp = bB + n * (BROW_W * 4);
                bh[nt][0] = *(const uint32_t*)(rowp + (ksl * 8 + cA) * 4);
                bh[nt][1] = *(const uint32_t*)(rowp + (ksl * 8 + cA + 4) * 4);
                bl[nt][0] = *(const uint32_t*)(rowp + BTILE_BYTES + (ksl * 8 + cA) * 4);
                bl[nt][1] = *(const uint32_t*)(rowp + BTILE_BYTES + (ksl * 8 + cA + 4) * 4);
            }
#pragma unroll
            for (int mt = 0; mt < 2; ++mt)
#pragma unroll
                for (int nt = 0; nt < 4; ++nt)
                    mma16(acc[mt][nt], ah[mt], bh[nt]);   // hi*hi
#pragma unroll
            for (int mt = 0; mt < 2; ++mt)
#pragma unroll
                for (int nt = 0; nt < 4; ++nt)
                    mma16(acc[mt][nt], ah[mt], bl[nt]);   // hi*lo
#pragma unroll
            for (int mt = 0; mt < 2; ++mt)
#pragma unroll
                for (int nt = 0; nt < 4; ++nt)
                    mma16(acc[mt][nt], al[mt], bh[nt]);   // lo*hi
        }
    }

    // ---- epilogue: raw partial tile -> g_part ----
    float* pt = g_part + (size_t)(c * 128 + ny) * 4096;
#pragma unroll
    for (int mt = 0; mt < 2; ++mt) {
        const int r0 = wm + mt * 16 + rA;
#pragma unroll
        for (int nt = 0; nt < 4; ++nt) {
            const int cl = wn + nt * 8 + cA * 2;
            float2 v0 = { acc[mt][nt][0], acc[mt][nt][1] };
            float2 v1 = { acc[mt][nt][2], acc[mt][nt][3] };
            *(float2*)(pt + r0 * 64 + cl)       = v0;
            *(float2*)(pt + (r0 + 8) * 64 + cl) = v1;
        }
    }
}

// =====================================================================
// Kernel 1b: deterministic split-K reduction + bias -> g_pre.
// =====================================================================
__global__ __launch_bounds__(256) void reduce_kernel(const float* __restrict__ b_enc)
{
    const int bx = blockIdx.x;
    const int g  = bx >> 7, ny = bx & 127;
    const int nch = 2 * (g + 1);
    const int cstart = g * (g + 1);
    const int tid = threadIdx.x;

    for (int idx = tid; idx < 4096; idx += 256) {
        const int row = idx >> 6, col = idx & 63;
        float s = b_enc[ny * 64 + col];
        const float* p = g_part + (size_t)(cstart * 128 + ny) * 4096 + idx;
        for (int cc = 0; cc < nch; ++cc)
            s += p[(size_t)cc * 128 * 4096];
        g_pre[(size_t)(g * 64 + row) * DSAE + ny * 64 + col] = s;
    }
}

// =====================================================================
// Kernel 2: TopK with exact-boundary refinement (fp64 recompute).
// Window: dlt = 1e-3 + 1.5e-4|v| (~20 sigma of bf16x3 error).
// =====================================================================
__global__ __launch_bounds__(256) void topk_kernel(
    const float* __restrict__ x,
    const float* __restrict__ W,
    const float* __restrict__ b_enc,
    float* __restrict__ z_out)
{
    const int row = blockIdx.x;           // t-major
    const int tid = threadIdx.x;
    const int t = row >> 3, b = row & 7;
    const int zrow = b * Tn + t;

    __shared__ unsigned us[DSAE];
    __shared__ unsigned hist[256];
    __shared__ unsigned s_prefix;
    __shared__ int      s_k;
    __shared__ int      cnts[256];
    __shared__ int      win_idx[WCAP];
    __shared__ float    win_f[WCAP];
    __shared__ double   win_e[WCAP];
    __shared__ unsigned char win_sel[WCAP];
    __shared__ double   redd[256];
    __shared__ int      s_nhi, s_w;

    const float* rp = g_pre + (size_t)row * DSAE;

    for (int j = tid; j < DSAE; j += 256) {
        unsigned u = __float_as_uint(rp[j]);
        us[j] = (u & 0x80000000u) ? ~u : (u | 0x80000000u);
    }
    if (tid == 0) { s_prefix = 0u; s_k = TOPK; }
    __syncthreads();

    for (int p = 24; p >= 0; p -= 8) {
        hist[tid] = 0u;
        __syncthreads();
        const unsigned pref = s_prefix;
        const int shift_hi = p + 8;
        for (int j = tid; j < DSAE; j += 256) {
            const unsigned u = us[j];
            const bool match = (shift_hi >= 32) || (((u ^ pref) >> shift_hi) == 0u);
            if (match) atomicAdd(&hist[(u >> p) & 255u], 1u);
        }
        __syncthreads();
        if (tid == 0) {
            int k = s_k;
            unsigned c = 0;
            for (int bin = 255; bin >= 0; --bin) {
                const unsigned h = hist[bin];
                if (c + h >= (unsigned)k) {
                    s_prefix = pref | ((unsigned)bin << p);
                    s_k = k - (int)c;
                    break;
                }
                c += h;
            }
        }
        __syncthreads();
    }

    const unsigned T = s_prefix;
    const unsigned iv = (T & 0x80000000u) ? (T & 0x7FFFFFFFu) : ~T;
    const float v64f = __uint_as_float(iv);
    const float dlt = 1e-3f + 1.5e-4f * fabsf(v64f);
    const float hiT = v64f + dlt, loT = v64f - dlt;

    int chi = 0, cwin = 0;
    for (int q = 0; q < DSAE / 256; ++q) {
        const int j = tid + q * 256;
        const unsigned u = us[j];
        const unsigned ui = (u & 0x80000000u) ? (u & 0x7FFFFFFFu) : ~u;
        const float f = __uint_as_float(ui);
        if (f > hiT) { if (f > 0.f) chi++; }
        else if (f >= loT) cwin++;
    }
    cnts[tid] = chi;
    hist[tid] = (unsigned)cwin;
    __syncthreads();
    if (tid == 0) {
        int run = 0;
        for (int i = 0; i < 256; ++i) { const int c = cnts[i]; cnts[i] = run; run += c; }
        s_nhi = run;
        int wr = 0;
        for (int i = 0; i < 256; ++i) { const int c = (int)hist[i]; hist[i] = (unsigned)wr; wr += c; }
        s_w = wr;
    }
    __syncthreads();

    int pos  = cnts[tid];
    int wpos = (int)hist[tid];
    for (int q = 0; q < DSAE / 256; ++q) {
        const int j = tid + q * 256;
        const unsigned u = us[j];
        const unsigned ui = (u & 0x80000000u) ? (u & 0x7FFFFFFFu) : ~u;
        const float f = __uint_as_float(ui);
        if (f > hiT) {
            if (f > 0.f) {
                if (pos < TOPK) {
                    g_idx[row * TOPK + pos] = j;
                    g_val[row * TOPK + pos] = f;
                }
                z_out[(size_t)zrow * DSAE + j] = f;
                pos++;
            }
        } else if (f >= loT) {
            if (wpos < WCAP) { win_idx[wpos] = j; win_f[wpos] = f; }
            wpos++;
        }
    }
    __syncthreads();

    const int nhi  = s_nhi;
    const int w    = (s_w < WCAP) ? s_w : WCAP;
    int need = TOPK - nhi;
    if (need < 0) need = 0;

    if (w > need) {
        const int kmax = (t + 1) * DIN;
        for (int c = 0; c < w; ++c) {
            const int s = win_idx[c];
            double p0 = 0.0, p1 = 0.0, p2 = 0.0, p3 = 0.0;
            int k = tid;
            for (; k + 768 < kmax; k += 1024) {
                {
                    const int off = k / DIN, d = k - off * DIN;
                    p0 += (double)x[(b * Tn + (t - off)) * DIN + d] * (double)W[(size_t)k * DSAE + s];
                }
                {
                    const int kk = k + 256;
                    const int off = kk / DIN, d = kk - off * DIN;
                    p1 += (double)x[(b * Tn + (t - off)) * DIN + d] * (double)W[(size_t)kk * DSAE + s];
                }
                {
                    const int kk = k + 512;
                    const int off = kk / DIN, d = kk - off * DIN;
                    p2 += (double)x[(b * Tn + (t - off)) * DIN + d] * (double)W[(size_t)kk * DSAE + s];
                }
                {
                    const int kk = k + 768;
                    const int off = kk / DIN, d = kk - off * DIN;
                    p3 += (double)x[(b * Tn + (t - off)) * DIN + d] * (double)W[(size_t)kk * DSAE + s];
                }
            }
            for (; k < kmax; k += 256) {
                const int off = k / DIN, d = k - off * DIN;
                p0 += (double)x[(b * Tn + (t - off)) * DIN + d] * (double)W[(size_t)k * DSAE + s];
            }
            redd[tid] = (p0 + p1) + (p2 + p3);
            __syncthreads();
#pragma unroll
            for (int st = 128; st > 0; st >>= 1) {
                if (tid < st) redd[tid] += redd[tid + st];
                __syncthreads();
            }
            if (tid == 0) win_e[c] = redd[0] + (double)b_enc[s];
            __syncthreads();
        }
        if (tid == 0) {
            for (int c = 0; c < w; ++c) win_sel[c] = 0;
            for (int r = 0; r < need; ++r) {
                int best = -1; double bv = -1e300;
                for (int c = 0; c < w; ++c)
                    if (!win_sel[c] && win_e[c] > bv) { bv = win_e[c]; best = c; }
                if (best >= 0) win_sel[best] = 1;
            }
        }
    } else {
        if (tid == 0) for (int c = 0; c < w; ++c) win_sel[c] = 1;
    }
    __syncthreads();

    if (tid == 0) {
        int p = (nhi > TOPK) ? TOPK : nhi;
        for (int c = 0; c < w; ++c) {
            if (win_sel[c]) {
                const float f = win_f[c];
                if (f > 0.f) {
                    if (p < TOPK) {
                        g_idx[row * TOPK + p] = win_idx[c];
                        g_val[row * TOPK + p] = f;
                    }
                    z_out[(size_t)zrow * DSAE + win_idx[c]] = f;
                    p++;
                }
            }
        }
        g_cnt[row] = (p > TOPK) ? TOPK : p;
    }
}

// =====================================================================
// Kernel 3: sparse decode + fused loss (deterministic integer atomics).
// =====================================================================
__global__ __launch_bounds__(256) void decode_kernel(
    const float* __restrict__ x,
    const float* __restrict__ W_dec,
    const float* __restrict__ b_dec,
    float* __restrict__ xhat,
    float* __restrict__ loss_out)
{
    const int row = blockIdx.x;                   // t-major
    const int bt  = (row & 7) * Tn + (row >> 3);  // (b,t)-major
    const int tid = threadIdx.x;

    __shared__ float sval[TOPK];
    __shared__ int   sidx[TOPK];
    __shared__ float red[256];

    const int cnt = g_cnt[row];
    if (tid < TOPK) {
        sval[tid] = (tid < cnt) ? g_val[row * TOPK + tid] : 0.f;
        sidx[tid] = (tid < cnt) ? g_idx[row * TOPK + tid] : 0;
    }
    __syncthreads();

    float a0 = b_dec[tid];
    float a1 = b_dec[tid + 256];
    float a2 = b_dec[tid + 512];

    for (int kk = 0; kk < cnt; ++kk) {
        const float v = sval[kk];
        const float* wd = W_dec + (size_t)sidx[kk] * DIN;
        a0 = fmaf(v, wd[tid],       a0);
        a1 = fmaf(v, wd[tid + 256], a1);
        a2 = fmaf(v, wd[tid + 512], a2);
    }

    const size_t bbase = (size_t)bt * DIN;
    xhat[bbase + tid]       = a0;
    xhat[bbase + tid + 256] = a1;
    xhat[bbase + tid + 512] = a2;

    const float d0 = a0 - x[bbase + tid];
    const float d1 = a1 - x[bbase + tid + 256];
    const float d2 = a2 - x[bbase + tid + 512];
    red[tid] = d0 * d0 + d1 * d1 + d2 * d2;
    __syncthreads();
#pragma unroll
    for (int st = 128; st > 0; st >>= 1) {
        if (tid < st) red[tid] += red[tid + st];
        __syncthreads();
    }
    if (tid == 0) {
        const unsigned long long q =
            (unsigned long long)__double2ll_rn((double)red[0] * 1048576.0);
        atomicAdd(&g_loss_acc, q);
        __threadfence();
        const int n = atomicAdd(&g_done_ctr, 1);
        if (n == MROWS - 1) {
            loss_out[0] = (float)((double)g_loss_acc *
                                  (1.0 / 1048576.0) * (1.0 / MROWS));
        }
    }
}

// =====================================================================
extern "C" void kernel_launch(void* const* d_in, const int* in_sizes, int n_in,
                              void* d_out, int out_size)
{
    const float* x      = (const float*)d_in[0];
    const float* W_enc  = (const float*)d_in[1];
    const float* W_dec  = (const float*)d_in[2];
    const float* b_enc  = (const float*)d_in[3];
    const float* b_dec  = (const float*)d_in[4];

    float* out  = (float*)d_out;
    float* loss = out;
    float* xhat = out + 1;
    float* z    = out + 1 + XHAT_ELEMS;

    cudaFuncSetAttribute(enc_mma_kernel,
                         cudaFuncAttributeMaxDynamicSharedMemorySize, SMEM_TOTAL);

    // Launch order: harness poison(#1), memset z(#2), dummies(#3-5),
    // enc(#6 <- ncu -s 5 -c 1 profiles this).
    cudaMemsetAsync(z, 0, Z_ELEMS * sizeof(float));
    dummy_kernel<<<1, 32>>>();
    dummy_kernel<<<1, 32>>>();
    dummy_kernel<<<1, 32>>>();

    dim3 grid(NCHUNK, DSAE / NTW);
    enc_mma_kernel<<<grid, 128, SMEM_TOTAL>>>(x, W_enc);
    reduce_kernel<<<512, 256>>>(b_enc);
    topk_kernel<<<MROWS, 256>>>(x, W_enc, b_enc, z);
    decode_kernel<<<MROWS, 256>>>(x, W_dec, b_dec, xhat, loss);
}

// round 16
// speedup vs baseline: 1.7374x; 1.7374x over previous
#include <cuda_runtime.h>
#include <cstdint>

// Problem constants
#define Bn    8
#define Tn    32
#define DIN   768
#define DSAE  8192
#define TOPK  64
#define MROWS 256
#define XHAT_ELEMS (MROWS * DIN)
#define Z_ELEMS    ((size_t)MROWS * DSAE)
#define WCAP  48

// GEMM tiling (R12/R14 skeleton: 128 threads, 64m x 64n)
#define MTW   64
#define NTW   64
#define KB    32
#define STAGES 4
#define KB_PER_CHUNK 96
#define NCHUNK 20
#define A_STR 36
#define B_STR 72
#define A_F   (MTW * A_STR)
#define B_F   (KB * B_STR)
#define STAGE_F (A_F + B_F)
#define A_BYTES (A_F * 4)
#define STAGE_BYTES (STAGE_F * 4)

// ---------------- scratch (no allocations allowed) ----------------
__device__ float g_pre[(size_t)MROWS * DSAE];                 // 8 MB, t-major
__device__ float g_part[(size_t)NCHUNK * 128 * 4096];         // 40 MB split-K partials
__device__ int   g_idx[MROWS * TOPK];
__device__ float g_val[MROWS * TOPK];
__device__ int   g_cnt[MROWS];
__device__ unsigned long long g_loss_acc;
__device__ int   g_done_ctr;

// ================= helpers (plain sm_80+ PTX only) =================
__device__ __forceinline__ uint32_t smem_u32(const void* p) {
    uint32_t a;
    asm("{ .reg .u64 t; cvta.to.shared.u64 t, %1; cvt.u32.u64 %0, t; }" : "=r"(a) : "l"(p));
    return a;
}
__device__ __forceinline__ void cp16(uint32_t dst, const void* src, int srcsize) {
    asm volatile("cp.async.cg.shared.global [%0], [%1], 16, %2;"
                 :: "r"(dst), "l"(src), "r"(srcsize) : "memory");
}
#define CP_COMMIT() asm volatile("cp.async.commit_group;" ::: "memory")
#define CP_WAIT2()  asm volatile("cp.async.wait_group 2;" ::: "memory")

// bf16 pair split: h = packed bf16-trunc(v0,v1); l = packed bf16-trunc(v0-h0, v1-h1)
__device__ __forceinline__ void bsplit2(float v0, float v1, uint32_t& h, uint32_t& l) {
    const uint32_t u0 = __float_as_uint(v0), u1 = __float_as_uint(v1);
    h = __byte_perm(u0, u1, 0x7632);
    const float l0 = v0 - __uint_as_float(u0 & 0xFFFF0000u);
    const float l1 = v1 - __uint_as_float(u1 & 0xFFFF0000u);
    l = __byte_perm(__float_as_uint(l0), __float_as_uint(l1), 0x7632);
}

// bf16 m16n8k16 mma
__device__ __forceinline__ void mma16(float* c, const uint32_t* a, const uint32_t* b) {
    asm volatile(
        "mma.sync.aligned.m16n8k16.row.col.f32.bf16.bf16.f32 "
        "{%0,%1,%2,%3}, {%4,%5,%6,%7}, {%8,%9}, {%0,%1,%2,%3};"
        : "+f"(c[0]), "+f"(c[1]), "+f"(c[2]), "+f"(c[3])
        : "r"(a[0]), "r"(a[1]), "r"(a[2]), "r"(a[3]), "r"(b[0]), "r"(b[1]));
}

// =====================================================================
// Stage copy: A 64m x 32k causal im2col (cp.async zero-fill); B 32k x 64n.
// =====================================================================
__device__ __forceinline__ void copy_stage(
    uint32_t sbase, int kb, int m0,
    const float* __restrict__ x, const float* __restrict__ W, int s0, int tid)
{
#pragma unroll
    for (int q = 0; q < 4; ++q) {
        const int ch  = tid + q * 128;
        const int row = ch >> 3, c4 = ch & 7;
        const int kg  = kb * KB + c4 * 4;
        const int off = kg / DIN;
        const int d   = kg - off * DIN;
        const int mrow = m0 + row;
        const int t = mrow >> 3, b = mrow & 7;
        const bool ok = (off <= t);
        const int  tt = ok ? (t - off) : 0;
        const float* src = x + ((b * Tn + tt) * DIN + d);
        cp16(sbase + row * (A_STR * 4) + c4 * 16, src, ok ? 16 : 0);
    }
#pragma unroll
    for (int q = 0; q < 4; ++q) {
        const int ch = tid + q * 128;
        const int kr = ch >> 4, c = ch & 15;
        const float* src = W + (size_t)(kb * KB + kr) * DSAE + s0 + c * 4;
        cp16(sbase + A_BYTES + kr * (B_STR * 4) + c * 16, src, 16);
    }
}

// =====================================================================
// Dummy kernel (ncu alignment so enc lands on profiled launch #6) + reset.
// =====================================================================
__global__ void dummy_kernel() {
    if (threadIdx.x == 0 && blockIdx.x == 0) { g_loss_acc = 0ULL; g_done_ctr = 0; }
}

// =====================================================================
// Kernel 1: encoder GEMM, bf16x3 emulation (hh+hl+lh, k16 mma), SPLIT-K.
// (R12/R14 version verbatim — measured 645.8-649.3 us.)
// =====================================================================
__global__ __launch_bounds__(128, 3) void enc_mma_kernel(
    const float* __restrict__ x,
    const float* __restrict__ W)
{
    extern __shared__ float sm[];
    const uint32_t smb = smem_u32(sm);
    const int tid = threadIdx.x, lane = tid & 31, wid = tid >> 5;
    const int c  = blockIdx.x;
    const int ny = blockIdx.y;
    const int s0 = ny * NTW;
    const int g  = (c < 2) ? 0 : (c < 6) ? 1 : (c < 12) ? 2 : 3;
    const int kb0 = (c - g * (g + 1)) * KB_PER_CHUNK;
    const int m0  = g * MTW;
    const int wm  = (wid & 1) * 32, wn = (wid >> 1) * 32;

    float acc[2][4][4];
#pragma unroll
    for (int a = 0; a < 2; ++a)
#pragma unroll
        for (int b = 0; b < 4; ++b)
#pragma unroll
            for (int cc = 0; cc < 4; ++cc) acc[a][b][cc] = 0.f;

#pragma unroll
    for (int p = 0; p < STAGES - 1; ++p) {
        copy_stage(smb + p * STAGE_BYTES, kb0 + p, m0, x, W, s0, tid);
        CP_COMMIT();
    }

    const int rA = lane >> 2;
    const int cA = lane & 3;

    for (int i = 0; i < KB_PER_CHUNK; ++i) {
        CP_WAIT2();
        __syncthreads();

        const int nx = i + STAGES - 1;
        if (nx < KB_PER_CHUNK)
            copy_stage(smb + (nx & 3) * STAGE_BYTES, kb0 + nx, m0, x, W, s0, tid);
        CP_COMMIT();

        const float* As = sm + (i & 3) * STAGE_F;
        const float* Bs = As + A_F;
        const float* Ar0 = As + (wm + rA) * A_STR + cA * 2;
        const float* Ar1 = As + (wm + 16 + rA) * A_STR + cA * 2;
        const float* Bc  = Bs + (cA * 2) * B_STR + wn + rA;

#pragma unroll
        for (int ksl = 0; ksl < 2; ++ksl) {
            const int kb16 = ksl * 16;
            uint32_t ah[2][4], al[2][4];
#pragma unroll
            for (int mt = 0; mt < 2; ++mt) {
                const float* ap = (mt == 0) ? Ar0 : Ar1;
                float2 p0 = *(const float2*)(ap + kb16);
                float2 p1 = *(const float2*)(ap + 8 * A_STR + kb16);
                float2 p2 = *(const float2*)(ap + kb16 + 8);
                float2 p3 = *(const float2*)(ap + 8 * A_STR + kb16 + 8);
                bsplit2(p0.x, p0.y, ah[mt][0], al[mt][0]);
                bsplit2(p1.x, p1.y, ah[mt][1], al[mt][1]);
                bsplit2(p2.x, p2.y, ah[mt][2], al[mt][2]);
                bsplit2(p3.x, p3.y, ah[mt][3], al[mt][3]);
            }
            uint32_t bh[4][2], bl[4][2];
#pragma unroll
            for (int nt = 0; nt < 4; ++nt) {
                const float* bp = Bc + kb16 * B_STR + nt * 8;
                bsplit2(bp[0],          bp[B_STR],     bh[nt][0], bl[nt][0]);
                bsplit2(bp[8 * B_STR],  bp[9 * B_STR], bh[nt][1], bl[nt][1]);
            }
#pragma unroll
            for (int mt = 0; mt < 2; ++mt)
#pragma unroll
                for (int nt = 0; nt < 4; ++nt)
                    mma16(acc[mt][nt], ah[mt], bh[nt]);   // hi*hi
#pragma unroll
            for (int mt = 0; mt < 2; ++mt)
#pragma unroll
                for (int nt = 0; nt < 4; ++nt)
                    mma16(acc[mt][nt], ah[mt], bl[nt]);   // hi*lo
#pragma unroll
            for (int mt = 0; mt < 2; ++mt)
#pragma unroll
                for (int nt = 0; nt < 4; ++nt)
                    mma16(acc[mt][nt], al[mt], bh[nt]);   // lo*hi
        }
    }

    // ---- epilogue: raw partial tile -> g_part ----
    float* pt = g_part + (size_t)(c * 128 + ny) * 4096;
#pragma unroll
    for (int mt = 0; mt < 2; ++mt) {
        const int r0 = wm + mt * 16 + rA;
#pragma unroll
        for (int nt = 0; nt < 4; ++nt) {
            const int cl = wn + nt * 8 + cA * 2;
            float2 v0 = { acc[mt][nt][0], acc[mt][nt][1] };
            float2 v1 = { acc[mt][nt][2], acc[mt][nt][3] };
            *(float2*)(pt + r0 * 64 + cl)       = v0;
            *(float2*)(pt + (r0 + 8) * 64 + cl) = v1;
        }
    }
}

// =====================================================================
// Kernel 1b: deterministic split-K reduction + bias -> g_pre.
// =====================================================================
__global__ __launch_bounds__(256) void reduce_kernel(const float* __restrict__ b_enc)
{
    const int bx = blockIdx.x;
    const int g  = bx >> 7, ny = bx & 127;
    const int nch = 2 * (g + 1);
    const int cstart = g * (g + 1);
    const int tid = threadIdx.x;

    for (int idx = tid; idx < 4096; idx += 256) {
        const int row = idx >> 6, col = idx & 63;
        float s = b_enc[ny * 64 + col];
        const float* p = g_part + (size_t)(cstart * 128 + ny) * 4096 + idx;
        for (int cc = 0; cc < nch; ++cc)
            s += p[(size_t)cc * 128 * 4096];
        g_pre[(size_t)(g * 64 + row) * DSAE + ny * 64 + col] = s;
    }
}

// =====================================================================
// Kernel 2: TopK with exact-boundary refinement (fp64 recompute).
// Window: dlt = 1e-3 + 1.5e-4|v| (R15-validated: selections identical).
// =====================================================================
__global__ __launch_bounds__(256) void topk_kernel(
    const float* __restrict__ x,
    const float* __restrict__ W,
    const float* __restrict__ b_enc,
    float* __restrict__ z_out)
{
    const int row = blockIdx.x;           // t-major
    const int tid = threadIdx.x;
    const int t = row >> 3, b = row & 7;
    const int zrow = b * Tn + t;

    __shared__ unsigned us[DSAE];
    __shared__ unsigned hist[256];
    __shared__ unsigned s_prefix;
    __shared__ int      s_k;
    __shared__ int      cnts[256];
    __shared__ int      win_idx[WCAP];
    __shared__ float    win_f[WCAP];
    __shared__ double   win_e[WCAP];
    __shared__ unsigned char win_sel[WCAP];
    __shared__ double   redd[256];
    __shared__ int      s_nhi, s_w;

    const float* rp = g_pre + (size_t)row * DSAE;

    for (int j = tid; j < DSAE; j += 256) {
        unsigned u = __float_as_uint(rp[j]);
        us[j] = (u & 0x80000000u) ? ~u : (u | 0x80000000u);
    }
    if (tid == 0) { s_prefix = 0u; s_k = TOPK; }
    __syncthreads();

    for (int p = 24; p >= 0; p -= 8) {
        hist[tid] = 0u;
        __syncthreads();
        const unsigned pref = s_prefix;
        const int shift_hi = p + 8;
        for (int j = tid; j < DSAE; j += 256) {
            const unsigned u = us[j];
            const bool match = (shift_hi >= 32) || (((u ^ pref) >> shift_hi) == 0u);
            if (match) atomicAdd(&hist[(u >> p) & 255u], 1u);
        }
        __syncthreads();
        if (tid == 0) {
            int k = s_k;
            unsigned c = 0;
            for (int bin = 255; bin >= 0; --bin) {
                const unsigned h = hist[bin];
                if (c + h >= (unsigned)k) {
                    s_prefix = pref | ((unsigned)bin << p);
                    s_k = k - (int)c;
                    break;
                }
                c += h;
            }
        }
        __syncthreads();
    }

    const unsigned T = s_prefix;
    const unsigned iv = (T & 0x80000000u) ? (T & 0x7FFFFFFFu) : ~T;
    const float v64f = __uint_as_float(iv);
    const float dlt = 1e-3f + 1.5e-4f * fabsf(v64f);
    const float hiT = v64f + dlt, loT = v64f - dlt;

    int chi = 0, cwin = 0;
    for (int q = 0; q < DSAE / 256; ++q) {
        const int j = tid + q * 256;
        const unsigned u = us[j];
        const unsigned ui = (u & 0x80000000u) ? (u & 0x7FFFFFFFu) : ~u;
        const float f = __uint_as_float(ui);
        if (f > hiT) { if (f > 0.f) chi++; }
        else if (f >= loT) cwin++;
    }
    cnts[tid] = chi;
    hist[tid] = (unsigned)cwin;
    __syncthreads();
    if (tid == 0) {
        int run = 0;
        for (int i = 0; i < 256; ++i) { const int c = cnts[i]; cnts[i] = run; run += c; }
        s_nhi = run;
        int wr = 0;
        for (int i = 0; i < 256; ++i) { const int c = (int)hist[i]; hist[i] = (unsigned)wr; wr += c; }
        s_w = wr;
    }
    __syncthreads();

    int pos  = cnts[tid];
    int wpos = (int)hist[tid];
    for (int q = 0; q < DSAE / 256; ++q) {
        const int j = tid + q * 256;
        const unsigned u = us[j];
        const unsigned ui = (u & 0x80000000u) ? (u & 0x7FFFFFFFu) : ~u;
        const float f = __uint_as_float(ui);
        if (f > hiT) {
            if (f > 0.f) {
                if (pos < TOPK) {
                    g_idx[row * TOPK + pos] = j;
                    g_val[row * TOPK + pos] = f;
                }
                z_out[(size_t)zrow * DSAE + j] = f;
                pos++;
            }
        } else if (f >= loT) {
            if (wpos < WCAP) { win_idx[wpos] = j; win_f[wpos] = f; }
            wpos++;
        }
    }
    __syncthreads();

    const int nhi  = s_nhi;
    const int w    = (s_w < WCAP) ? s_w : WCAP;
    int need = TOPK - nhi;
    if (need < 0) need = 0;

    if (w > need) {
        const int kmax = (t + 1) * DIN;
        for (int c = 0; c < w; ++c) {
            const int s = win_idx[c];
            double p0 = 0.0, p1 = 0.0, p2 = 0.0, p3 = 0.0;
            int k = tid;
            for (; k + 768 < kmax; k += 1024) {
                {
                    const int off = k / DIN, d = k - off * DIN;
                    p0 += (double)x[(b * Tn + (t - off)) * DIN + d] * (double)W[(size_t)k * DSAE + s];
                }
                {
                    const int kk = k + 256;
                    const int off = kk / DIN, d = kk - off * DIN;
                    p1 += (double)x[(b * Tn + (t - off)) * DIN + d] * (double)W[(size_t)kk * DSAE + s];
                }
                {
                    const int kk = k + 512;
                    const int off = kk / DIN, d = kk - off * DIN;
                    p2 += (double)x[(b * Tn + (t - off)) * DIN + d] * (double)W[(size_t)kk * DSAE + s];
                }
                {
                    const int kk = k + 768;
                    const int off = kk / DIN, d = kk - off * DIN;
                    p3 += (double)x[(b * Tn + (t - off)) * DIN + d] * (double)W[(size_t)kk * DSAE + s];
                }
            }
            for (; k < kmax; k += 256) {
                const int off = k / DIN, d = k - off * DIN;
                p0 += (double)x[(b * Tn + (t - off)) * DIN + d] * (double)W[(size_t)k * DSAE + s];
            }
            redd[tid] = (p0 + p1) + (p2 + p3);
            __syncthreads();
#pragma unroll
            for (int st = 128; st > 0; st >>= 1) {
                if (tid < st) redd[tid] += redd[tid + st];
                __syncthreads();
            }
            if (tid == 0) win_e[c] = redd[0] + (double)b_enc[s];
            __syncthreads();
        }
        if (tid == 0) {
            for (int c = 0; c < w; ++c) win_sel[c] = 0;
            for (int r = 0; r < need; ++r) {
                int best = -1; double bv = -1e300;
                for (int c = 0; c < w; ++c)
                    if (!win_sel[c] && win_e[c] > bv) { bv = win_e[c]; best = c; }
                if (best >= 0) win_sel[best] = 1;
            }
        }
    } else {
        if (tid == 0) for (int c = 0; c < w; ++c) win_sel[c] = 1;
    }
    __syncthreads();

    if (tid == 0) {
        int p = (nhi > TOPK) ? TOPK : nhi;
        for (int c = 0; c < w; ++c) {
            if (win_sel[c]) {
                const float f = win_f[c];
                if (f > 0.f) {
                    if (p < TOPK) {
                        g_idx[row * TOPK + p] = win_idx[c];
                        g_val[row * TOPK + p] = f;
                    }
                    z_out[(size_t)zrow * DSAE + win_idx[c]] = f;
                    p++;
                }
            }
        }
        g_cnt[row] = (p > TOPK) ? TOPK : p;
    }
}

// =====================================================================
// Kernel 3: sparse decode + fused loss (deterministic integer atomics).
// =====================================================================
__global__ __launch_bounds__(256) void decode_kernel(
    const float* __restrict__ x,
    const float* __restrict__ W_dec,
    const float* __restrict__ b_dec,
    float* __restrict__ xhat,
    float* __restrict__ loss_out)
{
    const int row = blockIdx.x;                   // t-major
    const int bt  = (row & 7) * Tn + (row >> 3);  // (b,t)-major
    const int tid = threadIdx.x;

    __shared__ float sval[TOPK];
    __shared__ int   sidx[TOPK];
    __shared__ float red[256];

    const int cnt = g_cnt[row];
    if (tid < TOPK) {
        sval[tid] = (tid < cnt) ? g_val[row * TOPK + tid] : 0.f;
        sidx[tid] = (tid < cnt) ? g_idx[row * TOPK + tid] : 0;
    }
    __syncthreads();

    float a0 = b_dec[tid];
    float a1 = b_dec[tid + 256];
    float a2 = b_dec[tid + 512];

    for (int kk = 0; kk < cnt; ++kk) {
        const float v = sval[kk];
        const float* wd = W_dec + (size_t)sidx[kk] * DIN;
        a0 = fmaf(v, wd[tid],       a0);
        a1 = fmaf(v, wd[tid + 256], a1);
        a2 = fmaf(v, wd[tid + 512], a2);
    }

    const size_t bbase = (size_t)bt * DIN;
    xhat[bbase + tid]       = a0;
    xhat[bbase + tid + 256] = a1;
    xhat[bbase + tid + 512] = a2;

    const float d0 = a0 - x[bbase + tid];
    const float d1 = a1 - x[bbase + tid + 256];
    const float d2 = a2 - x[bbase + tid + 512];
    red[tid] = d0 * d0 + d1 * d1 + d2 * d2;
    __syncthreads();
#pragma unroll
    for (int st = 128; st > 0; st >>= 1) {
        if (tid < st) red[tid] += red[tid + st];
        __syncthreads();
    }
    if (tid == 0) {
        const unsigned long long q =
            (unsigned long long)__double2ll_rn((double)red[0] * 1048576.0);
        atomicAdd(&g_loss_acc, q);
        __threadfence();
        const int n = atomicAdd(&g_done_ctr, 1);
        if (n == MROWS - 1) {
            loss_out[0] = (float)((double)g_loss_acc *
                                  (1.0 / 1048576.0) * (1.0 / MROWS));
        }
    }
}

// =====================================================================
extern "C" void kernel_launch(void* const* d_in, const int* in_sizes, int n_in,
                              void* d_out, int out_size)
{
    const float* x      = (const float*)d_in[0];
    const float* W_enc  = (const float*)d_in[1];
    const float* W_dec  = (const float*)d_in[2];
    const float* b_enc  = (const float*)d_in[3];
    const float* b_dec  = (const float*)d_in[4];

    float* out  = (float*)d_out;
    float* loss = out;
    float* xhat = out + 1;
    float* z    = out + 1 + XHAT_ELEMS;

    cudaFuncSetAttribute(enc_mma_kernel,
                         cudaFuncAttributeMaxDynamicSharedMemorySize,
                         STAGES * STAGE_BYTES);

    // Launch order: harness poison(#1), memset z(#2), dummies(#3-5),
    // enc(#6 <- ncu -s 5 -c 1 profiles this).
    cudaMemsetAsync(z, 0, Z_ELEMS * sizeof(float));
    dummy_kernel<<<1, 32>>>();
    dummy_kernel<<<1, 32>>>();
    dummy_kernel<<<1, 32>>>();

    dim3 grid(NCHUNK, DSAE / NTW);
    enc_mma_kernel<<<grid, 128, STAGES * STAGE_BYTES>>>(x, W_enc);
    reduce_kernel<<<512, 256>>>(b_enc);
    topk_kernel<<<MROWS, 256>>>(x, W_enc, b_enc, z);
    decode_kernel<<<MROWS, 256>>>(x, W_dec, b_dec, xhat, loss);
}

// round 17
// speedup vs baseline: 1.7450x; 1.0043x over previous
#include <cuda_runtime.h>
#include <cstdint>

// Problem constants
#define Bn    8
#define Tn    32
#define DIN   768
#define DSAE  8192
#define TOPK  64
#define MROWS 256
#define XHAT_ELEMS (MROWS * DIN)
#define Z_ELEMS    ((size_t)MROWS * DSAE)
#define WCAP  48

// GEMM tiling (R12/R14/R16 skeleton: 128 threads, 64m x 64n)
#define MTW   64
#define NTW   64
#define KB    32
#define STAGES 4
#define KB_PER_CHUNK 96
#define NCHUNK 20
#define A_STR 36
#define B_STR 72
#define A_F   (MTW * A_STR)
#define B_F   (KB * B_STR)
#define STAGE_F (A_F + B_F)
#define A_BYTES (A_F * 4)
#define STAGE_BYTES (STAGE_F * 4)

// ---------------- scratch (no allocations allowed) ----------------
__device__ float g_part[(size_t)NCHUNK * 128 * 4096];         // 40 MB split-K partials
__device__ unsigned long long g_loss_acc;
__device__ int   g_done_ctr;

// ================= helpers (plain sm_80+ PTX only) =================
__device__ __forceinline__ uint32_t smem_u32(const void* p) {
    uint32_t a;
    asm("{ .reg .u64 t; cvta.to.shared.u64 t, %1; cvt.u32.u64 %0, t; }" : "=r"(a) : "l"(p));
    return a;
}
__device__ __forceinline__ void cp16(uint32_t dst, const void* src, int srcsize) {
    asm volatile("cp.async.cg.shared.global [%0], [%1], 16, %2;"
                 :: "r"(dst), "l"(src), "r"(srcsize) : "memory");
}
#define CP_COMMIT() asm volatile("cp.async.commit_group;" ::: "memory")
#define CP_WAIT2()  asm volatile("cp.async.wait_group 2;" ::: "memory")

// bf16 pair split: h = packed bf16-trunc(v0,v1); l = packed bf16-trunc(v0-h0, v1-h1)
__device__ __forceinline__ void bsplit2(float v0, float v1, uint32_t& h, uint32_t& l) {
    const uint32_t u0 = __float_as_uint(v0), u1 = __float_as_uint(v1);
    h = __byte_perm(u0, u1, 0x7632);
    const float l0 = v0 - __uint_as_float(u0 & 0xFFFF0000u);
    const float l1 = v1 - __uint_as_float(u1 & 0xFFFF0000u);
    l = __byte_perm(__float_as_uint(l0), __float_as_uint(l1), 0x7632);
}

// bf16 m16n8k16 mma
__device__ __forceinline__ void mma16(float* c, const uint32_t* a, const uint32_t* b) {
    asm volatile(
        "mma.sync.aligned.m16n8k16.row.col.f32.bf16.bf16.f32 "
        "{%0,%1,%2,%3}, {%4,%5,%6,%7}, {%8,%9}, {%0,%1,%2,%3};"
        : "+f"(c[0]), "+f"(c[1]), "+f"(c[2]), "+f"(c[3])
        : "r"(a[0]), "r"(a[1]), "r"(a[2]), "r"(a[3]), "r"(b[0]), "r"(b[1]));
}

// =====================================================================
// Stage copy: A 64m x 32k causal im2col (cp.async zero-fill); B 32k x 64n.
// =====================================================================
__device__ __forceinline__ void copy_stage(
    uint32_t sbase, int kb, int m0,
    const float* __restrict__ x, const float* __restrict__ W, int s0, int tid)
{
#pragma unroll
    for (int q = 0; q < 4; ++q) {
        const int ch  = tid + q * 128;
        const int row = ch >> 3, c4 = ch & 7;
        const int kg  = kb * KB + c4 * 4;
        const int off = kg / DIN;
        const int d   = kg - off * DIN;
        const int mrow = m0 + row;
        const int t = mrow >> 3, b = mrow & 7;
        const bool ok = (off <= t);
        const int  tt = ok ? (t - off) : 0;
        const float* src = x + ((b * Tn + tt) * DIN + d);
        cp16(sbase + row * (A_STR * 4) + c4 * 16, src, ok ? 16 : 0);
    }
#pragma unroll
    for (int q = 0; q < 4; ++q) {
        const int ch = tid + q * 128;
        const int kr = ch >> 4, c = ch & 15;
        const float* src = W + (size_t)(kb * KB + kr) * DSAE + s0 + c * 4;
        cp16(sbase + A_BYTES + kr * (B_STR * 4) + c * 16, src, 16);
    }
}

// =====================================================================
// Dummy kernel (ncu alignment so enc lands on profiled launch #6) + reset.
// =====================================================================
__global__ void dummy_kernel() {
    if (threadIdx.x == 0 && blockIdx.x == 0) { g_loss_acc = 0ULL; g_done_ctr = 0; }
}

// =====================================================================
// Kernel 1: encoder GEMM, bf16x3 emulation (hh+hl+lh, k16 mma), SPLIT-K.
// (R12/R14/R16 version verbatim — measured 645.8-649.3 us.)
// =====================================================================
__global__ __launch_bounds__(128, 3) void enc_mma_kernel(
    const float* __restrict__ x,
    const float* __restrict__ W)
{
    extern __shared__ float sm[];
    const uint32_t smb = smem_u32(sm);
    const int tid = threadIdx.x, lane = tid & 31, wid = tid >> 5;
    const int c  = blockIdx.x;
    const int ny = blockIdx.y;
    const int s0 = ny * NTW;
    const int g  = (c < 2) ? 0 : (c < 6) ? 1 : (c < 12) ? 2 : 3;
    const int kb0 = (c - g * (g + 1)) * KB_PER_CHUNK;
    const int m0  = g * MTW;
    const int wm  = (wid & 1) * 32, wn = (wid >> 1) * 32;

    float acc[2][4][4];
#pragma unroll
    for (int a = 0; a < 2; ++a)
#pragma unroll
        for (int b = 0; b < 4; ++b)
#pragma unroll
            for (int cc = 0; cc < 4; ++cc) acc[a][b][cc] = 0.f;

#pragma unroll
    for (int p = 0; p < STAGES - 1; ++p) {
        copy_stage(smb + p * STAGE_BYTES, kb0 + p, m0, x, W, s0, tid);
        CP_COMMIT();
    }

    const int rA = lane >> 2;
    const int cA = lane & 3;

    for (int i = 0; i < KB_PER_CHUNK; ++i) {
        CP_WAIT2();
        __syncthreads();

        const int nx = i + STAGES - 1;
        if (nx < KB_PER_CHUNK)
            copy_stage(smb + (nx & 3) * STAGE_BYTES, kb0 + nx, m0, x, W, s0, tid);
        CP_COMMIT();

        const float* As = sm + (i & 3) * STAGE_F;
        const float* Bs = As + A_F;
        const float* Ar0 = As + (wm + rA) * A_STR + cA * 2;
        const float* Ar1 = As + (wm + 16 + rA) * A_STR + cA * 2;
        const float* Bc  = Bs + (cA * 2) * B_STR + wn + rA;

#pragma unroll
        for (int ksl = 0; ksl < 2; ++ksl) {
            const int kb16 = ksl * 16;
            uint32_t ah[2][4], al[2][4];
#pragma unroll
            for (int mt = 0; mt < 2; ++mt) {
                const float* ap = (mt == 0) ? Ar0 : Ar1;
                float2 p0 = *(const float2*)(ap + kb16);
                float2 p1 = *(const float2*)(ap + 8 * A_STR + kb16);
                float2 p2 = *(const float2*)(ap + kb16 + 8);
                float2 p3 = *(const float2*)(ap + 8 * A_STR + kb16 + 8);
                bsplit2(p0.x, p0.y, ah[mt][0], al[mt][0]);
                bsplit2(p1.x, p1.y, ah[mt][1], al[mt][1]);
                bsplit2(p2.x, p2.y, ah[mt][2], al[mt][2]);
                bsplit2(p3.x, p3.y, ah[mt][3], al[mt][3]);
            }
            uint32_t bh[4][2], bl[4][2];
#pragma unroll
            for (int nt = 0; nt < 4; ++nt) {
                const float* bp = Bc + kb16 * B_STR + nt * 8;
                bsplit2(bp[0],          bp[B_STR],     bh[nt][0], bl[nt][0]);
                bsplit2(bp[8 * B_STR],  bp[9 * B_STR], bh[nt][1], bl[nt][1]);
            }
#pragma unroll
            for (int mt = 0; mt < 2; ++mt)
#pragma unroll
                for (int nt = 0; nt < 4; ++nt)
                    mma16(acc[mt][nt], ah[mt], bh[nt]);   // hi*hi
#pragma unroll
            for (int mt = 0; mt < 2; ++mt)
#pragma unroll
                for (int nt = 0; nt < 4; ++nt)
                    mma16(acc[mt][nt], ah[mt], bl[nt]);   // hi*lo
#pragma unroll
            for (int mt = 0; mt < 2; ++mt)
#pragma unroll
                for (int nt = 0; nt < 4; ++nt)
                    mma16(acc[mt][nt], al[mt], bh[nt]);   // lo*hi
        }
    }

    // ---- epilogue: raw partial tile -> g_part ----
    float* pt = g_part + (size_t)(c * 128 + ny) * 4096;
#pragma unroll
    for (int mt = 0; mt < 2; ++mt) {
        const int r0 = wm + mt * 16 + rA;
#pragma unroll
        for (int nt = 0; nt < 4; ++nt) {
            const int cl = wn + nt * 8 + cA * 2;
            float2 v0 = { acc[mt][nt][0], acc[mt][nt][1] };
            float2 v1 = { acc[mt][nt][2], acc[mt][nt][3] };
            *(float2*)(pt + r0 * 64 + cl)       = v0;
            *(float2*)(pt + (r0 + 8) * 64 + cl) = v1;
        }
    }
}

// =====================================================================
// Kernel 2 (FUSED): split-K reduce + bias -> keys; radix TopK with
// exact-boundary refinement; sparse decode + loss. One block per row.
// Summation order identical to the old reduce_kernel -> bit-identical pre.
// =====================================================================
__global__ __launch_bounds__(256) void tail_kernel(
    const float* __restrict__ x,
    const float* __restrict__ W,
    const float* __restrict__ b_enc,
    const float* __restrict__ W_dec,
    const float* __restrict__ b_dec,
    float* __restrict__ z_out,
    float* __restrict__ xhat,
    float* __restrict__ loss_out)
{
    const int row = blockIdx.x;           // t-major
    const int tid = threadIdx.x;
    const int t = row >> 3, b = row & 7;
    const int zrow = b * Tn + t;          // (b,t)-major output row

    __shared__ unsigned us[DSAE];         // 32 KB monotone keys
    __shared__ unsigned hist[256];
    __shared__ unsigned s_prefix;
    __shared__ int      s_k;
    __shared__ int      cnts[256];
    __shared__ int      sel_idx[TOPK];
    __shared__ float    sel_val[TOPK];
    __shared__ int      win_idx[WCAP];
    __shared__ float    win_f[WCAP];
    __shared__ double   win_e[WCAP];
    __shared__ unsigned char win_sel[WCAP];
    __shared__ double   redd[256];
    __shared__ float    redf[256];
    __shared__ int      s_nhi, s_w, s_cnt;

    // ---- 1. pre = b_enc + sum of split-K partials (reduce_kernel order) ----
    {
        const int g = row >> 6, rin = row & 63;
        const int nch = 2 * (g + 1);
        const int cstart = g * (g + 1);
        for (int q = 0; q < DSAE / 256; ++q) {
            const int j = tid + q * 256;
            const int ny = j >> 6, cl = j & 63;
            float s = b_enc[j];
            const float* p = g_part + ((size_t)(cstart * 128 + ny)) * 4096 + rin * 64 + cl;
            for (int cc = 0; cc < nch; ++cc)
                s += p[(size_t)cc * 128 * 4096];
            unsigned u = __float_as_uint(s);
            us[j] = (u & 0x80000000u) ? ~u : (u | 0x80000000u);
        }
    }
    if (tid == 0) { s_prefix = 0u; s_k = TOPK; }
    __syncthreads();

    // ---- 2. radix select (4 x 8-bit passes) ----
    for (int p = 24; p >= 0; p -= 8) {
        hist[tid] = 0u;
        __syncthreads();
        const unsigned pref = s_prefix;
        const int shift_hi = p + 8;
        for (int j = tid; j < DSAE; j += 256) {
            const unsigned u = us[j];
            const bool match = (shift_hi >= 32) || (((u ^ pref) >> shift_hi) == 0u);
            if (match) atomicAdd(&hist[(u >> p) & 255u], 1u);
        }
        __syncthreads();
        if (tid == 0) {
            int k = s_k;
            unsigned c = 0;
            for (int bin = 255; bin >= 0; --bin) {
                const unsigned h = hist[bin];
                if (c + h >= (unsigned)k) {
                    s_prefix = pref | ((unsigned)bin << p);
                    s_k = k - (int)c;
                    break;
                }
                c += h;
            }
        }
        __syncthreads();
    }

    const unsigned T = s_prefix;
    const unsigned iv = (T & 0x80000000u) ? (T & 0x7FFFFFFFu) : ~T;
    const float v64f = __uint_as_float(iv);
    const float dlt = 1e-3f + 1.5e-4f * fabsf(v64f);
    const float hiT = v64f + dlt, loT = v64f - dlt;

    // ---- 3. classify ----
    int chi = 0, cwin = 0;
    for (int q = 0; q < DSAE / 256; ++q) {
        const int j = tid + q * 256;
        const unsigned u = us[j];
        const unsigned ui = (u & 0x80000000u) ? (u & 0x7FFFFFFFu) : ~u;
        const float f = __uint_as_float(ui);
        if (f > hiT) { if (f > 0.f) chi++; }
        else if (f >= loT) cwin++;
    }
    cnts[tid] = chi;
    hist[tid] = (unsigned)cwin;
    __syncthreads();
    if (tid == 0) {
        int run = 0;
        for (int i = 0; i < 256; ++i) { const int c = cnts[i]; cnts[i] = run; run += c; }
        s_nhi = run;
        int wr = 0;
        for (int i = 0; i < 256; ++i) { const int c = (int)hist[i]; hist[i] = (unsigned)wr; wr += c; }
        s_w = wr;
    }
    __syncthreads();

    int pos  = cnts[tid];
    int wpos = (int)hist[tid];
    for (int q = 0; q < DSAE / 256; ++q) {
        const int j = tid + q * 256;
        const unsigned u = us[j];
        const unsigned ui = (u & 0x80000000u) ? (u & 0x7FFFFFFFu) : ~u;
        const float f = __uint_as_float(ui);
        if (f > hiT) {
            if (f > 0.f) {
                if (pos < TOPK) { sel_idx[pos] = j; sel_val[pos] = f; }
                z_out[(size_t)zrow * DSAE + j] = f;
                pos++;
            }
        } else if (f >= loT) {
            if (wpos < WCAP) { win_idx[wpos] = j; win_f[wpos] = f; }
            wpos++;
        }
    }
    __syncthreads();

    const int nhi  = s_nhi;
    const int w    = (s_w < WCAP) ? s_w : WCAP;
    int need = TOPK - nhi;
    if (need < 0) need = 0;

    // ---- 4. exact fp64 boundary resolve ----
    if (w > need) {
        const int kmax = (t + 1) * DIN;
        for (int c = 0; c < w; ++c) {
            const int s = win_idx[c];
            double p0 = 0.0, p1 = 0.0, p2 = 0.0, p3 = 0.0;
            int k = tid;
            for (; k + 768 < kmax; k += 1024) {
                {
                    const int off = k / DIN, d = k - off * DIN;
                    p0 += (double)x[(b * Tn + (t - off)) * DIN + d] * (double)W[(size_t)k * DSAE + s];
                }
                {
                    const int kk = k + 256;
                    const int off = kk / DIN, d = kk - off * DIN;
                    p1 += (double)x[(b * Tn + (t - off)) * DIN + d] * (double)W[(size_t)kk * DSAE + s];
                }
                {
                    const int kk = k + 512;
                    const int off = kk / DIN, d = kk - off * DIN;
                    p2 += (double)x[(b * Tn + (t - off)) * DIN + d] * (double)W[(size_t)kk * DSAE + s];
                }
                {
                    const int kk = k + 768;
                    const int off = kk / DIN, d = kk - off * DIN;
                    p3 += (double)x[(b * Tn + (t - off)) * DIN + d] * (double)W[(size_t)kk * DSAE + s];
                }
            }
            for (; k < kmax; k += 256) {
                const int off = k / DIN, d = k - off * DIN;
                p0 += (double)x[(b * Tn + (t - off)) * DIN + d] * (double)W[(size_t)k * DSAE + s];
            }
            redd[tid] = (p0 + p1) + (p2 + p3);
            __syncthreads();
#pragma unroll
            for (int st = 128; st > 0; st >>= 1) {
                if (tid < st) redd[tid] += redd[tid + st];
                __syncthreads();
            }
            if (tid == 0) win_e[c] = redd[0] + (double)b_enc[s];
            __syncthreads();
        }
        if (tid == 0) {
            for (int c = 0; c < w; ++c) win_sel[c] = 0;
            for (int r = 0; r < need; ++r) {
                int best = -1; double bv = -1e300;
                for (int c = 0; c < w; ++c)
                    if (!win_sel[c] && win_e[c] > bv) { bv = win_e[c]; best = c; }
                if (best >= 0) win_sel[best] = 1;
            }
        }
    } else {
        if (tid == 0) for (int c = 0; c < w; ++c) win_sel[c] = 1;
    }
    __syncthreads();

    if (tid == 0) {
        int p = (nhi > TOPK) ? TOPK : nhi;
        for (int c = 0; c < w; ++c) {
            if (win_sel[c]) {
                const float f = win_f[c];
                if (f > 0.f) {
                    if (p < TOPK) { sel_idx[p] = win_idx[c]; sel_val[p] = f; }
                    z_out[(size_t)zrow * DSAE + win_idx[c]] = f;
                    p++;
                }
            }
        }
        s_cnt = (p > TOPK) ? TOPK : p;
    }
    __syncthreads();

    // ---- 5. sparse decode + per-row loss (old decode_kernel body) ----
    const int cnt = s_cnt;
    float a0 = b_dec[tid];
    float a1 = b_dec[tid + 256];
    float a2 = b_dec[tid + 512];

    for (int kk = 0; kk < cnt; ++kk) {
        const float v = sel_val[kk];
        const float* wd = W_dec + (size_t)sel_idx[kk] * DIN;
        a0 = fmaf(v, wd[tid],       a0);
        a1 = fmaf(v, wd[tid + 256], a1);
        a2 = fmaf(v, wd[tid + 512], a2);
    }

    const size_t bbase = (size_t)zrow * DIN;
    xhat[bbase + tid]       = a0;
    xhat[bbase + tid + 256] = a1;
    xhat[bbase + tid + 512] = a2;

    const float d0 = a0 - x[bbase + tid];
    const float d1 = a1 - x[bbase + tid + 256];
    const float d2 = a2 - x[bbase + tid + 512];
    redf[tid] = d0 * d0 + d1 * d1 + d2 * d2;
    __syncthreads();
#pragma unroll
    for (int st = 128; st > 0; st >>= 1) {
        if (tid < st) redf[tid] += redf[tid + st];
        __syncthreads();
    }
    if (tid == 0) {
        const unsigned long long q =
            (unsigned long long)__double2ll_rn((double)redf[0] * 1048576.0);
        atomicAdd(&g_loss_acc, q);
        __threadfence();
        const int n = atomicAdd(&g_done_ctr, 1);
        if (n == MROWS - 1) {
            loss_out[0] = (float)((double)g_loss_acc *
                                  (1.0 / 1048576.0) * (1.0 / MROWS));
        }
    }
}

// =====================================================================
extern "C" void kernel_launch(void* const* d_in, const int* in_sizes, int n_in,
                              void* d_out, int out_size)
{
    const float* x      = (const float*)d_in[0];
    const float* W_enc  = (const float*)d_in[1];
    const float* W_dec  = (const float*)d_in[2];
    const float* b_enc  = (const float*)d_in[3];
    const float* b_dec  = (const float*)d_in[4];

    float* out  = (float*)d_out;
    float* loss = out;
    float* xhat = out + 1;
    float* z    = out + 1 + XHAT_ELEMS;

    cudaFuncSetAttribute(enc_mma_kernel,
                         cudaFuncAttributeMaxDynamicSharedMemorySize,
                         STAGES * STAGE_BYTES);

    // Launch order: harness poison(#1), memset z(#2), dummies(#3-5),
    // enc(#6 <- ncu -s 5 -c 1 profiles this), tail(#7).
    cudaMemsetAsync(z, 0, Z_ELEMS * sizeof(float));
    dummy_kernel<<<1, 32>>>();
    dummy_kernel<<<1, 32>>>();
    dummy_kernel<<<1, 32>>>();

    dim3 grid(NCHUNK, DSAE / NTW);
    enc_mma_kernel<<<grid, 128, STAGES * STAGE_BYTES>>>(x, W_enc);
    tail_kernel<<<MROWS, 256>>>(x, W_enc, b_enc, W_dec, b_dec, z, xhat, loss);
}